// round 1
// baseline (speedup 1.0000x reference)
#include <cuda_runtime.h>
#include <cstdint>

#define BB 64
#define HH 1024
#define WW 1024
#define NN 256
#define MAX_ITERS 20
#define W9 (1.0f/9.0f)

// scratch: end coordinates after gravity_move (x,y per point)
__device__ int g_end[BB * NN * 2];

// ---------------------------------------------------------------------------
// Kernel 1: gravity_move, one warp per point. Smoothing computed on the fly
// from a cooperatively-loaded 9x9 raw tile (zero padding == conv 'SAME').
// ---------------------------------------------------------------------------
__global__ void __launch_bounds__(256) gravity_kernel(
    const float* __restrict__ depth, const int* __restrict__ points)
{
    const int w    = threadIdx.x >> 5;
    const int lane = threadIdx.x & 31;
    const int pidx = blockIdx.x * 8 + w;          // grid sized exactly B*N/8
    const int b    = pidx >> 8;                   // N = 256
    const float* dep = depth + (size_t)b * HH * WW;

    int px = points[pidx * 2 + 0];
    int py = points[pidx * 2 + 1];

    __shared__ float tile[8][9][12];              // 9x9 raw window, padded row

    const float NEG_INF = __int_as_float(0xff800000);

    for (int it = 0; it < MAX_ITERS; ++it) {
        const int by = py - 4, bx = px - 4;

        // cooperative load of raw 9x9 (81 values), zero outside image
        #pragma unroll
        for (int rnd = 0; rnd < 3; ++rnd) {
            int e = rnd * 32 + lane;
            if (e < 81) {
                int r = e / 9, c = e - r * 9;
                int gy = by + r, gx = bx + c;
                float v = 0.0f;
                if (gy >= 0 && gy < HH && gx >= 0 && gx < WW)
                    v = __ldg(dep + gy * WW + gx);
                tile[w][r][c] = v;
            }
        }
        __syncwarp();

        // 49 candidate cells, <=2 per lane. Smoothed value at CLIPPED coords.
        float bestv = NEG_INF;
        int   besti = 64;
        #pragma unroll
        for (int pass = 0; pass < 2; ++pass) {
            int cell = lane + pass * 32;
            if (cell < 49) {
                int dy = cell / 7 - 3;
                int dx = cell - (cell / 7) * 7 - 3;
                int yc = min(max(py + dy, 0), HH - 1);
                int xc = min(max(px + dx, 0), WW - 1);
                int ty = yc - by;                 // in [1,7]
                int tx = xc - bx;                 // in [1,7]
                float acc = 0.0f;
                #pragma unroll
                for (int i = 0; i < 3; ++i)
                    #pragma unroll
                    for (int j = 0; j < 3; ++j)
                        acc = fmaf(tile[w][ty - 1 + i][tx - 1 + j], W9, acc);
                if (acc > bestv || (acc == bestv && cell < besti)) {
                    bestv = acc; besti = cell;
                }
            }
        }

        // warp argmax with first-index tie-break (matches jnp.argmax)
        #pragma unroll
        for (int off = 16; off; off >>= 1) {
            float vo = __shfl_xor_sync(0xffffffffu, bestv, off);
            int   io = __shfl_xor_sync(0xffffffffu, besti, off);
            if (vo > bestv || (vo == bestv && io < besti)) { bestv = vo; besti = io; }
        }

        int dy = besti / 7 - 3;
        int dx = besti - (besti / 7) * 7 - 3;
        int ny = min(max(py + dy, 0), HH - 1);
        int nx = min(max(px + dx, 0), WW - 1);
        bool moved = (nx != px) | (ny != py);
        px = nx; py = ny;
        __syncwarp();
        if (!moved) break;                        // fixed point: stays fixed
    }

    if (lane == 0) {
        g_end[pidx * 2 + 0] = px;
        g_end[pidx * 2 + 1] = py;
    }
}

// ---------------------------------------------------------------------------
// Kernel 2: resolve_overlaps (exact integer squared-distance arithmetic) +
// peak lookup (on-the-fly smoothing at the final coordinate).
// One block of N threads per batch.
// ---------------------------------------------------------------------------
__global__ void __launch_bounds__(NN) resolve_kernel(
    const float* __restrict__ depth, const int* __restrict__ points,
    float* __restrict__ out)
{
    const int b = blockIdx.x;
    const int i = threadIdx.x;
    const int base = b * NN;

    __shared__ int ex[NN], ey[NN], sx[NN], sy[NN];
    __shared__ int winner[NN];

    ex[i] = g_end[(base + i) * 2 + 0];
    ey[i] = g_end[(base + i) * 2 + 1];
    sx[i] = points[(base + i) * 2 + 0];
    sy[i] = points[(base + i) * 2 + 1];
    __syncthreads();

    const int exi = ex[i], eyi = ey[i];
    int cnt = 0, leader = -1;
    int bestd = 0x7fffffff, win = 0;

    #pragma unroll 4
    for (int j = 0; j < NN; ++j) {
        int ddx = exi - ex[j], ddy = eyi - ey[j];
        int de  = ddx * ddx + ddy * ddy;
        if (de < 4) {                              // dist < 2.0  <=>  sq < 4
            cnt++;
            if (leader < 0) leader = j;            // argmax(ov): first true
            int sdx = sx[j] - exi, sdy = sy[j] - eyi;
            int sd  = sdx * sdx + sdy * sdy;
            if (sd < bestd) { bestd = sd; win = j; }   // argmin: first min
        }
    }
    winner[i] = win;
    __syncthreads();

    const bool has = (cnt > 1);                    // self always overlaps
    const int  wol = winner[leader];
    const bool keep = (i == wol);

    int fx, fy;
    if (has) {
        if (keep) { fx = ex[leader]; fy = ey[leader]; }
        else      { fx = sx[i];      fy = sy[i];      }
    } else        { fx = exi;        fy = eyi;        }

    // peak = smoothed depth at final (fy, fx), zero padding, row-major fma
    const float* dep = depth + (size_t)b * HH * WW;
    float acc = 0.0f;
    #pragma unroll
    for (int u = -1; u <= 1; ++u)
        #pragma unroll
        for (int v = -1; v <= 1; ++v) {
            int gy = fy + u, gx = fx + v;
            float val = (gy >= 0 && gy < HH && gx >= 0 && gx < WW)
                            ? __ldg(dep + gy * WW + gx) : 0.0f;
            acc = fmaf(val, W9, acc);
        }

    // output layout: end (B,N,2) as float, then peak (B,N)
    out[(base + i) * 2 + 0] = (float)fx;
    out[(base + i) * 2 + 1] = (float)fy;
    out[BB * NN * 2 + base + i] = acc;
}

// ---------------------------------------------------------------------------
extern "C" void kernel_launch(void* const* d_in, const int* in_sizes, int n_in,
                              void* d_out, int out_size)
{
    const float* depth  = (const float*)d_in[0];   // (64,1,1024,1024) f32
    const int*   points = (const int*)d_in[1];     // (64,256,2) i32
    float* out = (float*)d_out;                    // 49152 f32: end ++ peak

    gravity_kernel<<<(BB * NN) / 8, 256>>>(depth, points);
    resolve_kernel<<<BB, NN>>>(depth, points, out);
}

// round 2
// speedup vs baseline: 1.0830x; 1.0830x over previous
#include <cuda_runtime.h>
#include <cstdint>

#define BB 64
#define HH 1024
#define WW 1024
#define NN 256
#define MAX_ITERS 20
#define W9 (1.0f/9.0f)

// scratch
__device__ int g_end[BB * NN * 2];   // end coords after gravity (x,y)
__device__ int g_meta[BB * NN];      // winner | leader<<8 | has<<16

// ---------------------------------------------------------------------------
// Kernel 1: gravity_move, one warp per point. Per-lane index math hoisted out
// of the loop; warp-uniform interior fast path removes guards and clips.
// ---------------------------------------------------------------------------
__global__ void __launch_bounds__(256) gravity_kernel(
    const float* __restrict__ depth, const int* __restrict__ points)
{
    const int w    = threadIdx.x >> 5;
    const int lane = threadIdx.x & 31;
    const int pidx = blockIdx.x * 8 + w;          // grid = B*N/8
    const int b    = pidx >> 8;                   // N = 256
    const float* dep = depth + (size_t)b * HH * WW;

    int px = points[pidx * 2 + 0];
    int py = points[pidx * 2 + 1];

    __shared__ float tile[8][9][12];              // 9x9 raw window, padded pitch
    float* T = &tile[w][0][0];

    // ---- loop-invariant per-lane constants ----
    // load slots: elements lane, lane+32, lane+64 of the 81-element tile
    const int r0 = lane / 9,        c0 = lane - r0 * 9;
    const int e1 = lane + 32;
    const int r1 = e1 / 9,          c1 = e1 - r1 * 9;
    const int e2 = lane + 64;
    const int r2 = e2 / 9,          c2 = e2 - r2 * 9;
    const bool l3 = (lane < 17);                  // e2 < 81
    const int go0 = r0 * WW + c0,   so0 = r0 * 12 + c0;
    const int go1 = r1 * WW + c1,   so1 = r1 * 12 + c1;
    const int go2 = r2 * WW + c2,   so2 = r2 * 12 + c2;

    // candidate cells: lane and lane+32 (cells 0..48)
    const int cA  = lane;
    const int rA  = cA / 7;
    const int dyA = rA - 3,  dxA = cA - rA * 7 - 3;
    const int cB  = lane + 32;
    const int rB  = cB / 7;
    const int dyB = rB - 3,  dxB = cB - rB * 7 - 3;
    const bool hasB = (cB < 49);
    const int sAo = (dyA + 3) * 12 + (dxA + 3);   // top-left of 3x3 in tile
    const int sBo = (dyB + 3) * 12 + (dxB + 3);

    const float NEG_INF = __int_as_float(0xff800000);

    for (int it = 0; it < MAX_ITERS; ++it) {
        const int by = py - 4, bx = px - 4;
        const bool interior = (px >= 4) & (px <= WW - 5) &
                              (py >= 4) & (py <= HH - 5);   // warp-uniform

        if (interior) {
            const float* base = dep + by * WW + bx;
            T[so0] = __ldg(base + go0);
            T[so1] = __ldg(base + go1);
            if (l3) T[so2] = __ldg(base + go2);
        } else {
            {
                int gy = by + r0, gx = bx + c0;
                T[so0] = (gy >= 0 && gy < HH && gx >= 0 && gx < WW)
                             ? __ldg(dep + gy * WW + gx) : 0.0f;
            }
            {
                int gy = by + r1, gx = bx + c1;
                T[so1] = (gy >= 0 && gy < HH && gx >= 0 && gx < WW)
                             ? __ldg(dep + gy * WW + gx) : 0.0f;
            }
            if (l3) {
                int gy = by + r2, gx = bx + c2;
                T[so2] = (gy >= 0 && gy < HH && gx >= 0 && gx < WW)
                             ? __ldg(dep + gy * WW + gx) : 0.0f;
            }
        }
        __syncwarp();

        float bestv;
        int   besti;
        if (interior) {
            const float* p = T + sAo;
            float acc = 0.0f;
            #pragma unroll
            for (int i2 = 0; i2 < 3; ++i2)
                #pragma unroll
                for (int j2 = 0; j2 < 3; ++j2)
                    acc = fmaf(p[i2 * 12 + j2], W9, acc);
            bestv = acc; besti = cA;
            if (hasB) {
                const float* q = T + sBo;
                float a2 = 0.0f;
                #pragma unroll
                for (int i2 = 0; i2 < 3; ++i2)
                    #pragma unroll
                    for (int j2 = 0; j2 < 3; ++j2)
                        a2 = fmaf(q[i2 * 12 + j2], W9, a2);
                if (a2 > bestv) { bestv = a2; besti = cB; }  // cB>cA: tie keeps A
            }
        } else {
            // border path: clipped candidate coords (duplicates -> exact ties,
            // first-index tie-break applied below)
            {
                int yc = min(max(py + dyA, 0), HH - 1);
                int xc = min(max(px + dxA, 0), WW - 1);
                const float* p = T + (yc - by - 1) * 12 + (xc - bx - 1);
                float acc = 0.0f;
                #pragma unroll
                for (int i2 = 0; i2 < 3; ++i2)
                    #pragma unroll
                    for (int j2 = 0; j2 < 3; ++j2)
                        acc = fmaf(p[i2 * 12 + j2], W9, acc);
                bestv = acc; besti = cA;
            }
            if (hasB) {
                int yc = min(max(py + dyB, 0), HH - 1);
                int xc = min(max(px + dxB, 0), WW - 1);
                const float* q = T + (yc - by - 1) * 12 + (xc - bx - 1);
                float a2 = 0.0f;
                #pragma unroll
                for (int i2 = 0; i2 < 3; ++i2)
                    #pragma unroll
                    for (int j2 = 0; j2 < 3; ++j2)
                        a2 = fmaf(q[i2 * 12 + j2], W9, a2);
                if (a2 > bestv) { bestv = a2; besti = cB; }
            }
        }

        // warp argmax, first-index tie-break (matches jnp.argmax)
        #pragma unroll
        for (int off = 16; off; off >>= 1) {
            float vo = __shfl_xor_sync(0xffffffffu, bestv, off);
            int   io = __shfl_xor_sync(0xffffffffu, besti, off);
            if (vo > bestv || (vo == bestv && io < besti)) { bestv = vo; besti = io; }
        }

        int rr = besti / 7;
        int ny = min(max(py + rr - 3, 0), HH - 1);
        int nx = min(max(px + besti - rr * 7 - 3, 0), WW - 1);
        bool moved = (nx != px) | (ny != py);
        px = nx; py = ny;
        __syncwarp();
        if (!moved) break;                        // fixed point stays fixed
    }

    if (lane == 0) {
        g_end[pidx * 2 + 0] = px;
        g_end[pidx * 2 + 1] = py;
    }
}

// ---------------------------------------------------------------------------
// Kernel 2: pairwise overlap stats, one WARP per point (lane covers 8 j's).
// Exact integer squared distances; first-index tie-breaks preserved.
// ---------------------------------------------------------------------------
__global__ void __launch_bounds__(256) pairwise_kernel(
    const int* __restrict__ points)
{
    const int w    = threadIdx.x >> 5;
    const int lane = threadIdx.x & 31;
    const int blkInBatch = blockIdx.x & 31;       // 32 blocks per batch
    const int b    = blockIdx.x >> 5;
    const int base = b * NN;

    __shared__ int ex[NN], ey[NN], sx[NN], sy[NN];
    const int t = threadIdx.x;
    ex[t] = g_end[(base + t) * 2 + 0];
    ey[t] = g_end[(base + t) * 2 + 1];
    sx[t] = points[(base + t) * 2 + 0];
    sy[t] = points[(base + t) * 2 + 1];
    __syncthreads();

    const int i   = blkInBatch * 8 + w;
    const int exi = ex[i], eyi = ey[i];

    int cnt = 0, minlead = 0x7fffffff;
    int bestd = 0x7fffffff, bestj = 0x7fffffff;

    #pragma unroll
    for (int k = 0; k < 8; ++k) {
        int j   = lane + 32 * k;                  // ascending j per lane
        int ddx = exi - ex[j], ddy = eyi - ey[j];
        int de  = ddx * ddx + ddy * ddy;
        if (de < 4) {                             // dist < 2.0  <=>  sq < 4
            cnt++;
            minlead = min(minlead, j);            // argmax(ov) = first True
            int sdx = sx[j] - exi, sdy = sy[j] - eyi;
            int sd  = sdx * sdx + sdy * sdy;
            if (sd < bestd || (sd == bestd && j < bestj)) { bestd = sd; bestj = j; }
        }
    }

    #pragma unroll
    for (int off = 16; off; off >>= 1) {
        cnt     += __shfl_xor_sync(0xffffffffu, cnt, off);
        minlead  = min(minlead, __shfl_xor_sync(0xffffffffu, minlead, off));
        int od   = __shfl_xor_sync(0xffffffffu, bestd, off);
        int oj   = __shfl_xor_sync(0xffffffffu, bestj, off);
        if (od < bestd || (od == bestd && oj < bestj)) { bestd = od; bestj = oj; }
    }

    if (lane == 0)
        g_meta[base + i] = bestj | (minlead << 8) | ((cnt > 1) << 16);
}

// ---------------------------------------------------------------------------
// Kernel 3: finalize coordinates + peak (on-the-fly 3x3 smoothing, exact
// row-major fma chain as validated in round 1).
// ---------------------------------------------------------------------------
__global__ void __launch_bounds__(128) finalize_kernel(
    const float* __restrict__ depth, const int* __restrict__ points,
    float* __restrict__ out)
{
    const int gid  = blockIdx.x * 128 + threadIdx.x;   // 0..16383
    const int b    = gid >> 8;
    const int base = b * NN;
    const int i    = gid & 255;

    const int meta   = g_meta[gid];
    const int leader = (meta >> 8) & 0xff;
    const bool has   = (meta >> 16) & 1;
    const int wol    = g_meta[base + leader] & 0xff;   // winner[leader]

    int fx, fy;
    if (has) {
        if (i == wol) {
            fx = g_end[(base + leader) * 2 + 0];
            fy = g_end[(base + leader) * 2 + 1];
        } else {
            fx = points[gid * 2 + 0];
            fy = points[gid * 2 + 1];
        }
    } else {
        fx = g_end[gid * 2 + 0];
        fy = g_end[gid * 2 + 1];
    }

    const float* dep = depth + (size_t)b * HH * WW;
    float acc = 0.0f;
    #pragma unroll
    for (int u = -1; u <= 1; ++u)
        #pragma unroll
        for (int v = -1; v <= 1; ++v) {
            int gy = fy + u, gx = fx + v;
            float val = (gy >= 0 && gy < HH && gx >= 0 && gx < WW)
                            ? __ldg(dep + gy * WW + gx) : 0.0f;
            acc = fmaf(val, W9, acc);
        }

    out[gid * 2 + 0] = (float)fx;
    out[gid * 2 + 1] = (float)fy;
    out[BB * NN * 2 + gid] = acc;
}

// ---------------------------------------------------------------------------
extern "C" void kernel_launch(void* const* d_in, const int* in_sizes, int n_in,
                              void* d_out, int out_size)
{
    const float* depth  = (const float*)d_in[0];   // (64,1,1024,1024) f32
    const int*   points = (const int*)d_in[1];     // (64,256,2) i32
    float* out = (float*)d_out;                    // end (B,N,2) ++ peak (B,N)

    gravity_kernel <<<(BB * NN) / 8, 256>>>(depth, points);
    pairwise_kernel<<<BB * 32,       256>>>(points);
    finalize_kernel<<<(BB * NN) / 128, 128>>>(depth, points, out);
}